// round 6
// baseline (speedup 1.0000x reference)
#include <cuda_runtime.h>
#include <cuda_bf16.h>

// ---------------------------------------------------------------------------
// Problem constants
// ---------------------------------------------------------------------------
#define NN      20000
#define TT      64
#define FF      128
#define BB      8192
#define KK      32
#define QQ      (3*BB)            // 24576
#define WWIN    64
#define MD      64
#define QK      (QQ*KK)           // 786432
#define TILE_E  64                // edges per block (= 2 full queries)
#define TILES2  (QK/TILE_E)       // 12288 tiles per direction
#define SMEM_K2 91136             // dynamic smem bytes for edge kernel

// ---------------------------------------------------------------------------
// Device scratch (static __device__ arrays — allocation APIs are forbidden)
// ---------------------------------------------------------------------------
__device__ int   g_mask_mode;                 // 0=u8, 1=i32, 2=f32
__device__ float g_demb[2*65*64];             // per-dir (delta_emb@w1_delta + b1)
__device__ float g_hsum[2*(size_t)QQ*64];     // per-(dir,query) sum of relu hidden
__device__ int   g_cnt[2*QQ];                 // per-(dir,query) valid-edge count
__device__ float g_feat[(size_t)QQ*256];      // [x_vt | m_in | m_out]
__device__ float g_u1[(size_t)QQ*128];        // combine hidden 1
__device__ float g_feat2[(size_t)BB*193];     // scorer features (col 192 unused)

// ---------------------------------------------------------------------------
// f32x2 helpers (sm_103a packed fp32 — 2x FFMA throughput)
// ---------------------------------------------------------------------------
__device__ __forceinline__ unsigned long long ffma2(unsigned long long a,
                                                    unsigned long long b,
                                                    unsigned long long c) {
    unsigned long long d;
    asm("fma.rn.f32x2 %0, %1, %2, %3;" : "=l"(d) : "l"(a), "l"(b), "l"(c));
    return d;
}
__device__ __forceinline__ unsigned long long dup2(float v) {
    unsigned long long r;
    asm("mov.b64 %0, {%1, %2};" : "=l"(r) : "f"(v), "f"(v));
    return r;
}
__device__ __forceinline__ float2 unpack2(unsigned long long v) {
    float2 r;
    asm("mov.b64 {%0, %1}, %2;" : "=f"(r.x), "=f"(r.y) : "l"(v));
    return r;
}

__device__ __forceinline__ int read_mask(const void* p, int idx, int mode) {
    if (mode == 1) return ((const int*)p)[idx] != 0;
    if (mode == 2) return ((const float*)p)[idx] != 0.0f;
    return ((const unsigned char*)p)[idx] != 0;
}

// ---------------------------------------------------------------------------
// K0: classify mask serialization (u8 / i32 / f32). Reads QK bytes worth of
// words, which is within the buffer for every candidate dtype.
// ---------------------------------------------------------------------------
__global__ void its_detect_kernel(const unsigned int* __restrict__ m) {
    __shared__ int not01, not0f;
    if (threadIdx.x == 0) { not01 = 0; not0f = 0; }
    __syncthreads();
    int l01 = 0, l0f = 0;
    for (int i = threadIdx.x; i < QK/4; i += blockDim.x) {
        unsigned v = m[i];
        if (v > 1u) l01 = 1;
        if (v != 0u && v != 0x3F800000u) l0f = 1;
    }
    if (l01) not01 = 1;
    if (l0f) not0f = 1;
    __syncthreads();
    if (threadIdx.x == 0)
        g_mask_mode = (!not01) ? 1 : ((!not0f) ? 2 : 0);
}

// ---------------------------------------------------------------------------
// K1: delta tables: g_demb[dir][d][j] = delta_emb[d] @ w1[128:144, :] + b1[j]
// ---------------------------------------------------------------------------
__global__ void its_tables_kernel(const float* __restrict__ demb,
                                  const float* __restrict__ piw1, const float* __restrict__ pib1,
                                  const float* __restrict__ pow1, const float* __restrict__ pob1) {
    int dir = blockIdx.x;
    const float* w1 = dir ? pow1 : piw1;
    const float* b1 = dir ? pob1 : pib1;
    float* out = g_demb + dir * (65*64);
    for (int idx = threadIdx.x; idx < 65*64; idx += blockDim.x) {
        int d = idx >> 6, j = idx & 63;
        float acc = b1[j];
#pragma unroll
        for (int dd = 0; dd < 16; dd++)
            acc += demb[d*16 + dd] * w1[(128 + dd)*64 + j];
        out[idx] = acc;
    }
}

// ---------------------------------------------------------------------------
// K2: edge aggregation. One block = one direction x 64 edges (2 queries).
// Gather x rows -> smem transposed [k][e], FFMA2 GEMM vs w1[:128] -> z,
// + demb[delta], relu, masked sum per query (deterministic, no atomics).
// ---------------------------------------------------------------------------
__global__ void __launch_bounds__(256, 2)
its_edge_kernel(const float* __restrict__ x,
                const int* __restrict__ in_u,  const int* __restrict__ in_tau,
                const void* __restrict__ in_mask,
                const int* __restrict__ out_u, const int* __restrict__ out_tau,
                const void* __restrict__ out_mask,
                const int* __restrict__ times,
                const float* __restrict__ piw1, const float* __restrict__ pow1) {
    extern __shared__ float sm[];
    float* As    = sm;               // [128 k][68]  (64 edges + pad)
    float* Bs    = As + 128*68;      // [128 k][68]  (64 j + pad)
    float* sdemb = Bs + 128*68;      // [65][64]
    float* spart = sdemb + 65*64;    // [16 groups][64]
    int* sdelta  = (int*)(spart + 16*64);  // [64]
    int* srow    = sdelta + 64;            // [64]
    int* smask   = srow + 64;              // [64]

    int bid  = blockIdx.x;
    int dir  = (bid >= TILES2) ? 1 : 0;
    int tile = bid - dir * TILES2;
    const int*  uu = dir ? out_u   : in_u;
    const int*  tt = dir ? out_tau : in_tau;
    const void* mm = dir ? out_mask : in_mask;
    const float* w1 = dir ? pow1 : piw1;
    const float* gd = g_demb + dir * 4160;
    int tid = threadIdx.x;
    int mode = g_mask_mode;

    // Stage w1 rows 0..127 (first 8192 floats of the 144x64 matrix)
    for (int i = tid; i < 2048; i += 256) {
        float4 v = ((const float4*)w1)[i];
        int k = i >> 4, j = (i & 15) * 4;
        *(float4*)(Bs + k*68 + j) = v;
    }
    // Stage delta table
    for (int i = tid; i < 4160; i += 256) sdemb[i] = gd[i];

    // Edge metadata
    if (tid < 64) {
        int e = tid;
        int s = tile*TILE_E + e;
        int q = s >> 5;
        int t = times[q];
        int u = uu[s], ta = tt[s];
        int d = dir ? (ta - t) : (t - ta);
        d = d < 0 ? 0 : (d > WWIN ? WWIN : d);
        sdelta[e] = d;
        srow[e]   = u*TT + ta;
        smask[e]  = read_mask(mm, s, mode);
    }
    __syncthreads();

    // Valid-edge counts
    if (tid < 2) {
        int c = 0;
#pragma unroll
        for (int i = 0; i < 32; i++) c += smask[tid*32 + i];
        g_cnt[dir*QQ + tile*2 + tid] = c;
    }

    // Gather x rows -> As transposed [k][e]; zero masked-out edges
    {
        int e = tid >> 2, h = tid & 3;
        if (smask[e]) {
            const float4* src = (const float4*)(x + (size_t)srow[e]*128) + h*8;
#pragma unroll
            for (int i = 0; i < 8; i++) {
                float4 v = src[i];
                int k0 = h*32 + i*4;
                As[(k0+0)*68 + e] = v.x;
                As[(k0+1)*68 + e] = v.y;
                As[(k0+2)*68 + e] = v.z;
                As[(k0+3)*68 + e] = v.w;
            }
        } else {
#pragma unroll
            for (int i = 0; i < 8; i++) {
                int k0 = h*32 + i*4;
                As[(k0+0)*68 + e] = 0.0f;
                As[(k0+1)*68 + e] = 0.0f;
                As[(k0+2)*68 + e] = 0.0f;
                As[(k0+3)*68 + e] = 0.0f;
            }
        }
    }
    __syncthreads();

    // GEMM: thread = 4 edges (2 FFMA2 pairs) x 4 j
    int r0 = (tid >> 4) * 4;     // edge base (within one query: groups of 4)
    int o0 = (tid & 15) * 4;     // j base
    unsigned long long acc[2][4];
#pragma unroll
    for (int p = 0; p < 2; p++)
#pragma unroll
        for (int j = 0; j < 4; j++) acc[p][j] = 0ull;

#pragma unroll 8
    for (int k = 0; k < 128; k++) {
        ulonglong2 a = *(const ulonglong2*)(As + k*68 + r0);
        float4 bv = *(const float4*)(Bs + k*68 + o0);
        unsigned long long b0 = dup2(bv.x), b1 = dup2(bv.y);
        unsigned long long b2 = dup2(bv.z), b3 = dup2(bv.w);
        acc[0][0] = ffma2(a.x, b0, acc[0][0]);
        acc[0][1] = ffma2(a.x, b1, acc[0][1]);
        acc[0][2] = ffma2(a.x, b2, acc[0][2]);
        acc[0][3] = ffma2(a.x, b3, acc[0][3]);
        acc[1][0] = ffma2(a.y, b0, acc[1][0]);
        acc[1][1] = ffma2(a.y, b1, acc[1][1]);
        acc[1][2] = ffma2(a.y, b2, acc[1][2]);
        acc[1][3] = ffma2(a.y, b3, acc[1][3]);
    }

    // + demb[delta], relu, masked partial sums (4 edges of one query)
    float part[4] = {0.f, 0.f, 0.f, 0.f};
#pragma unroll
    for (int p = 0; p < 2; p++) {
        int e0 = r0 + 2*p, e1 = e0 + 1;
        float2 c0 = unpack2(acc[p][0]);
        float2 c1 = unpack2(acc[p][1]);
        float2 c2 = unpack2(acc[p][2]);
        float2 c3 = unpack2(acc[p][3]);
        if (smask[e0]) {
            const float* dr = sdemb + sdelta[e0]*64 + o0;
            part[0] += fmaxf(c0.x + dr[0], 0.f);
            part[1] += fmaxf(c1.x + dr[1], 0.f);
            part[2] += fmaxf(c2.x + dr[2], 0.f);
            part[3] += fmaxf(c3.x + dr[3], 0.f);
        }
        if (smask[e1]) {
            const float* dr = sdemb + sdelta[e1]*64 + o0;
            part[0] += fmaxf(c0.y + dr[0], 0.f);
            part[1] += fmaxf(c1.y + dr[1], 0.f);
            part[2] += fmaxf(c2.y + dr[2], 0.f);
            part[3] += fmaxf(c3.y + dr[3], 0.f);
        }
    }
    int te = tid >> 4;
    spart[te*64 + o0 + 0] = part[0];
    spart[te*64 + o0 + 1] = part[1];
    spart[te*64 + o0 + 2] = part[2];
    spart[te*64 + o0 + 3] = part[3];
    __syncthreads();

    // Deterministic reduce: 8 groups per query
    if (tid < 128) {
        int q = tid >> 6, j = tid & 63;
        float s = 0.f;
#pragma unroll
        for (int g = 0; g < 8; g++) s += spart[(q*8 + g)*64 + j];
        g_hsum[(size_t)dir*QQ*64 + (size_t)(tile*2 + q)*64 + j] = s;
    }
}

// ---------------------------------------------------------------------------
// K3: per-query m_in/m_out (hsum @ w2 / cnt + b2) + x_vt gather -> g_feat[Q,256]
// Block = 16 queries, 256 threads.
// ---------------------------------------------------------------------------
__global__ void __launch_bounds__(256)
its_combine_a_kernel(const float* __restrict__ x,
                     const int* __restrict__ node_ids, const int* __restrict__ times,
                     const float* __restrict__ piw2, const float* __restrict__ pib2,
                     const float* __restrict__ pow2, const float* __restrict__ pob2) {
    __shared__ float s_w2[2*64*68];
    __shared__ float s_hs[2*16*64];
    __shared__ float s_b2[2*64];
    __shared__ int   s_cnt[2*16];

    int qb = blockIdx.x * 16;
    int tid = threadIdx.x;

    for (int i = tid; i < 4096; i += 256) {
        int k = i >> 6, j = i & 63;
        s_w2[k*68 + j]        = piw2[i];
        s_w2[4352 + k*68 + j] = pow2[i];
    }
    if (tid < 64) { s_b2[tid] = pib2[tid]; s_b2[64 + tid] = pob2[tid]; }
    for (int i = tid; i < 1024; i += 256) {
        int qi = i >> 6, j = i & 63;
        s_hs[i]        = g_hsum[(size_t)(qb + qi)*64 + j];
        s_hs[1024 + i] = g_hsum[(size_t)QQ*64 + (size_t)(qb + qi)*64 + j];
    }
    if (tid < 32) {
        int dir = tid >> 4, qi = tid & 15;
        s_cnt[tid] = g_cnt[dir*QQ + qb + qi];
    }
    __syncthreads();

    // m = hsum @ w2 / max(cnt,1) + (cnt>0)*b2
    {
        int r = tid >> 3, c = tid & 7;           // r: 32 (dir,query) rows; c: 8 col-groups
        int dir = r >> 4, qi = r & 15;
        const float* hs = s_hs + dir*1024 + qi*64;
        const float* w2 = s_w2 + dir*4352;
        float acc[8] = {0,0,0,0,0,0,0,0};
#pragma unroll 8
        for (int k = 0; k < 64; k++) {
            float h = hs[k];
            const float* wr = w2 + k*68 + c*8;
            float4 w0 = *(const float4*)wr;
            float4 w1 = *(const float4*)(wr + 4);
            acc[0] += h*w0.x; acc[1] += h*w0.y; acc[2] += h*w0.z; acc[3] += h*w0.w;
            acc[4] += h*w1.x; acc[5] += h*w1.y; acc[6] += h*w1.z; acc[7] += h*w1.w;
        }
        int cnt = s_cnt[dir*16 + qi];
        float inv = 1.0f / (float)(cnt > 1 ? cnt : 1);
        float bsc = cnt > 0 ? 1.0f : 0.0f;
        float* dst = g_feat + (size_t)(qb + qi)*256 + 128 + dir*64 + c*8;
#pragma unroll
        for (int j = 0; j < 8; j++)
            dst[j] = acc[j]*inv + bsc * s_b2[dir*64 + c*8 + j];
    }

    // x_vt gather (16 q x 128 floats)
    {
        int qi = tid >> 4, part = tid & 15;
        int q = qb + qi;
        const float* src = x + (size_t)node_ids[q]*8192 + (size_t)times[q]*128 + part*8;
        float* dst = g_feat + (size_t)q*256 + part*8;
        float4 a = ((const float4*)src)[0];
        float4 b = ((const float4*)src)[1];
        ((float4*)dst)[0] = a;
        ((float4*)dst)[1] = b;
    }
}

// ---------------------------------------------------------------------------
// K4: u1 = relu(feat @ cw1 + cb1)   [Q,256]@[256,128], FFMA2 tiled GEMM
// Block = 64 q x 128 j, 256 threads, thread = 4 q x 8 j.
// ---------------------------------------------------------------------------
__global__ void __launch_bounds__(256)
its_gemm1_kernel(const float* __restrict__ cw1, const float* __restrict__ cb1) {
    __shared__ float As[32*68];    // [k][q]
    __shared__ float Bs[32*128];   // [k][j]
    int qb = blockIdx.x * 64;
    int tid = threadIdx.x;
    int qg = (tid >> 4) * 4;
    int j0 = (tid & 15) * 8;

    unsigned long long acc[4][4];
#pragma unroll
    for (int a = 0; a < 4; a++)
#pragma unroll
        for (int b = 0; b < 4; b++) acc[a][b] = 0ull;

    for (int kc = 0; kc < 256; kc += 32) {
        {   // stage A transposed
            int q = tid >> 2, kq = tid & 3;
            const float* src = g_feat + (size_t)(qb + q)*256 + kc + kq*8;
            float4 v0 = ((const float4*)src)[0];
            float4 v1 = ((const float4*)src)[1];
            int k0 = kq*8;
            As[(k0+0)*68 + q] = v0.x; As[(k0+1)*68 + q] = v0.y;
            As[(k0+2)*68 + q] = v0.z; As[(k0+3)*68 + q] = v0.w;
            As[(k0+4)*68 + q] = v1.x; As[(k0+5)*68 + q] = v1.y;
            As[(k0+6)*68 + q] = v1.z; As[(k0+7)*68 + q] = v1.w;
        }
        {   // stage B
            int k = tid >> 3, jb = (tid & 7) * 16;
            const float4* src = (const float4*)(cw1 + (size_t)(kc + k)*128 + jb);
            float4* dst = (float4*)(Bs + k*128 + jb);
            dst[0] = src[0]; dst[1] = src[1]; dst[2] = src[2]; dst[3] = src[3];
        }
        __syncthreads();
#pragma unroll
        for (int k = 0; k < 32; k++) {
            float4 av = *(const float4*)(As + k*68 + qg);
            ulonglong2 bA = *(const ulonglong2*)(Bs + k*128 + j0);
            ulonglong2 bB = *(const ulonglong2*)(Bs + k*128 + j0 + 4);
            unsigned long long a0 = dup2(av.x), a1 = dup2(av.y);
            unsigned long long a2 = dup2(av.z), a3 = dup2(av.w);
            acc[0][0] = ffma2(a0, bA.x, acc[0][0]); acc[0][1] = ffma2(a0, bA.y, acc[0][1]);
            acc[0][2] = ffma2(a0, bB.x, acc[0][2]); acc[0][3] = ffma2(a0, bB.y, acc[0][3]);
            acc[1][0] = ffma2(a1, bA.x, acc[1][0]); acc[1][1] = ffma2(a1, bA.y, acc[1][1]);
            acc[1][2] = ffma2(a1, bB.x, acc[1][2]); acc[1][3] = ffma2(a1, bB.y, acc[1][3]);
            acc[2][0] = ffma2(a2, bA.x, acc[2][0]); acc[2][1] = ffma2(a2, bA.y, acc[2][1]);
            acc[2][2] = ffma2(a2, bB.x, acc[2][2]); acc[2][3] = ffma2(a2, bB.y, acc[2][3]);
            acc[3][0] = ffma2(a3, bA.x, acc[3][0]); acc[3][1] = ffma2(a3, bA.y, acc[3][1]);
            acc[3][2] = ffma2(a3, bB.x, acc[3][2]); acc[3][3] = ffma2(a3, bB.y, acc[3][3]);
        }
        __syncthreads();
    }

#pragma unroll
    for (int jp = 0; jp < 4; jp++) {
        int j = j0 + jp*2;
        float b0 = cb1[j], b1 = cb1[j+1];
#pragma unroll
        for (int qi = 0; qi < 4; qi++) {
            float2 v = unpack2(acc[qi][jp]);
            float r0 = v.x + b0; r0 = r0 > 0.f ? r0 : 0.f;
            float r1 = v.y + b1; r1 = r1 > 0.f ? r1 : 0.f;
            float* dst = g_u1 + (size_t)(qb + qg + qi)*128 + j;
            dst[0] = r0; dst[1] = r1;
        }
    }
}

// ---------------------------------------------------------------------------
// K5: h = relu(u1 @ cw2 + cb2)  [Q,128]@[128,64] -> scatter into g_feat2
// Block = 64 q x 64 j, 256 threads, thread = 4 q x 4 j.
// ---------------------------------------------------------------------------
__global__ void __launch_bounds__(256)
its_gemm2_kernel(const float* __restrict__ cw2, const float* __restrict__ cb2) {
    __shared__ float As[32*68];
    __shared__ float Bs[32*64];
    int qb = blockIdx.x * 64;
    int tid = threadIdx.x;
    int qg = (tid >> 4) * 4;
    int j0 = (tid & 15) * 4;

    float acc[4][4];
#pragma unroll
    for (int a = 0; a < 4; a++)
#pragma unroll
        for (int b = 0; b < 4; b++) acc[a][b] = 0.f;

    for (int kc = 0; kc < 128; kc += 32) {
        {
            int q = tid >> 2, kq = tid & 3;
            const float* src = g_u1 + (size_t)(qb + q)*128 + kc + kq*8;
            float4 v0 = ((const float4*)src)[0];
            float4 v1 = ((const float4*)src)[1];
            int k0 = kq*8;
            As[(k0+0)*68 + q] = v0.x; As[(k0+1)*68 + q] = v0.y;
            As[(k0+2)*68 + q] = v0.z; As[(k0+3)*68 + q] = v0.w;
            As[(k0+4)*68 + q] = v1.x; As[(k0+5)*68 + q] = v1.y;
            As[(k0+6)*68 + q] = v1.z; As[(k0+7)*68 + q] = v1.w;
        }
        {
            int k = tid >> 3, jb = (tid & 7) * 8;
            const float4* src = (const float4*)(cw2 + (size_t)(kc + k)*64 + jb);
            float4* dst = (float4*)(Bs + k*64 + jb);
            dst[0] = src[0]; dst[1] = src[1];
        }
        __syncthreads();
#pragma unroll
        for (int k = 0; k < 32; k++) {
            float4 av = *(const float4*)(As + k*68 + qg);
            float4 bv = *(const float4*)(Bs + k*64 + j0);
            acc[0][0] += av.x*bv.x; acc[0][1] += av.x*bv.y; acc[0][2] += av.x*bv.z; acc[0][3] += av.x*bv.w;
            acc[1][0] += av.y*bv.x; acc[1][1] += av.y*bv.y; acc[1][2] += av.y*bv.z; acc[1][3] += av.y*bv.w;
            acc[2][0] += av.z*bv.x; acc[2][1] += av.z*bv.y; acc[2][2] += av.z*bv.z; acc[2][3] += av.z*bv.w;
            acc[3][0] += av.w*bv.x; acc[3][1] += av.w*bv.y; acc[3][2] += av.w*bv.z; acc[3][3] += av.w*bv.w;
        }
        __syncthreads();
    }

#pragma unroll
    for (int qi = 0; qi < 4; qi++) {
        int gq = qb + qg + qi;
        int bb = gq / 3;
        int slot = gq - bb*3;
        float* dst = g_feat2 + (size_t)bb*193 + slot*64 + j0;
#pragma unroll
        for (int j = 0; j < 4; j++) {
            float h = acc[qi][j] + cb2[j0 + j];
            dst[j] = h > 0.f ? h : 0.f;
        }
    }
}

// ---------------------------------------------------------------------------
// K6: out[b] = relu(feat2 @ sw1 + sb1) @ sw2 + sb2   (warp per b)
// ---------------------------------------------------------------------------
__global__ void __launch_bounds__(256)
its_score_kernel(const float* __restrict__ sw1, const float* __restrict__ sb1,
                 const float* __restrict__ sw2, const float* __restrict__ sb2,
                 const float* __restrict__ d_norm, float* __restrict__ out) {
    __shared__ float srow[8*200];
    int tid = threadIdx.x;
    int w = tid >> 5, lane = tid & 31;
    int b = blockIdx.x * 8 + w;

    for (int k = lane; k < 192; k += 32)
        srow[w*200 + k] = g_feat2[(size_t)b*193 + k];
    if (lane == 0) srow[w*200 + 192] = d_norm[b];
    __syncwarp();

    float a0 = 0.f, a1 = 0.f, a2 = 0.f, a3 = 0.f;
    for (int k = 0; k < 193; k++) {
        float f = srow[w*200 + k];
        float4 wv = *(const float4*)(sw1 + (size_t)k*128 + lane*4);
        a0 += f*wv.x; a1 += f*wv.y; a2 += f*wv.z; a3 += f*wv.w;
    }
    int j = lane * 4;
    float v0 = a0 + sb1[j+0]; v0 = v0 > 0.f ? v0 : 0.f;
    float v1 = a1 + sb1[j+1]; v1 = v1 > 0.f ? v1 : 0.f;
    float v2 = a2 + sb1[j+2]; v2 = v2 > 0.f ? v2 : 0.f;
    float v3 = a3 + sb1[j+3]; v3 = v3 > 0.f ? v3 : 0.f;
    float4 w2v = *(const float4*)(sw2 + j);
    float p = v0*w2v.x + v1*w2v.y + v2*w2v.z + v3*w2v.w;
#pragma unroll
    for (int off = 16; off > 0; off >>= 1)
        p += __shfl_xor_sync(0xffffffffu, p, off);
    if (lane == 0) out[b] = p + sb2[0];
}

// ---------------------------------------------------------------------------
// kernel_launch
// ---------------------------------------------------------------------------
extern "C" void kernel_launch(void* const* d_in, const int* in_sizes, int n_in,
                              void* d_out, int out_size) {
    const float* x       = (const float*)d_in[0];
    const float* d_norm  = (const float*)d_in[1];
    const float* demb    = (const float*)d_in[2];
    const float* piw1    = (const float*)d_in[3];
    const float* pib1    = (const float*)d_in[4];
    const float* piw2    = (const float*)d_in[5];
    const float* pib2    = (const float*)d_in[6];
    const float* pow1    = (const float*)d_in[7];
    const float* pob1    = (const float*)d_in[8];
    const float* pow2    = (const float*)d_in[9];
    const float* pob2    = (const float*)d_in[10];
    const float* cw1     = (const float*)d_in[11];
    const float* cb1     = (const float*)d_in[12];
    const float* cw2     = (const float*)d_in[13];
    const float* cb2     = (const float*)d_in[14];
    const float* sw1     = (const float*)d_in[15];
    const float* sb1     = (const float*)d_in[16];
    const float* sw2     = (const float*)d_in[17];
    const float* sb2     = (const float*)d_in[18];
    const int* node_ids  = (const int*)d_in[19];
    const int* times     = (const int*)d_in[20];
    const int* in_u      = (const int*)d_in[21];
    const int* in_tau    = (const int*)d_in[22];
    const void* in_mask  = d_in[23];
    const int* out_u     = (const int*)d_in[24];
    const int* out_tau   = (const int*)d_in[25];
    const void* out_mask = d_in[26];
    float* out = (float*)d_out;

    cudaFuncSetAttribute(its_edge_kernel,
                         cudaFuncAttributeMaxDynamicSharedMemorySize, SMEM_K2);

    its_detect_kernel<<<1, 256>>>((const unsigned int*)in_mask);
    its_tables_kernel<<<2, 256>>>(demb, piw1, pib1, pow1, pob1);
    its_edge_kernel<<<2*TILES2, 256, SMEM_K2>>>(x,
        in_u, in_tau, in_mask, out_u, out_tau, out_mask, times, piw1, pow1);
    its_combine_a_kernel<<<QQ/16, 256>>>(x, node_ids, times, piw2, pib2, pow2, pob2);
    its_gemm1_kernel<<<QQ/64, 256>>>(cw1, cb1);
    its_gemm2_kernel<<<QQ/64, 256>>>(cw2, cb2);
    its_score_kernel<<<BB/8, 256>>>(sw1, sb1, sw2, sb2, d_norm, out);
}